// round 16
// baseline (speedup 1.0000x reference)
#include <cuda_runtime.h>
#include <cstdint>

#define IMG    256
#define NPIX   (IMG*IMG)
#define BS     8
#define LEN    64
#define KSEL   5
#define NPAIR  (BS*LEN)
#define CHUNKS 8
#define GP     4                      // pairs per CTA
#define GROUPS (LEN/GP)               // 16
#define THREADS 256
#define F4_PER_CHUNK (NPIX/4/CHUNKS)  // 2048 float4 per chunk
#define ITERS (F4_PER_CHUNK/THREADS)  // 8
#define P1_ITERS 2                    // pass-1 subsample: first 1/4 of chunk
#define CAP    192                    // candidate buffer per pair per CTA
#define NCTAS  (CHUNKS*GROUPS*BS)     // 1024

// partial top-5 per (pair, chunk), packed key = (float_bits(d)<<32)|idx
__device__ unsigned long long g_part[NPAIR][CHUNKS][KSEL];
__device__ int g_done;                // zero-init; reset by last CTA each launch

// ---------------- packed f32x2 helpers (bitwise identical to 2x scalar) ----
__device__ __forceinline__ unsigned long long pk2(float lo, float hi) {
    unsigned long long r;
    asm("mov.b64 %0,{%1,%2};" : "=l"(r) : "f"(lo), "f"(hi));
    return r;
}
__device__ __forceinline__ void upk2(unsigned long long v, float& lo, float& hi) {
    asm("mov.b64 {%0,%1},%2;" : "=f"(lo), "=f"(hi) : "l"(v));
}
__device__ __forceinline__ unsigned long long add2(unsigned long long a, unsigned long long b) {
    unsigned long long r;
    asm("add.rn.f32x2 %0,%1,%2;" : "=l"(r) : "l"(a), "l"(b));
    return r;
}
__device__ __forceinline__ unsigned long long mul2(unsigned long long a, unsigned long long b) {
    unsigned long long r;
    asm("mul.rn.f32x2 %0,%1,%2;" : "=l"(r) : "l"(a), "l"(b));
    return r;
}
__device__ __forceinline__ unsigned long long fma2(unsigned long long a, unsigned long long b,
                                                   unsigned long long c) {
    unsigned long long r;
    asm("fma.rn.f32x2 %0,%1,%2,%3;" : "=l"(r) : "l"(a), "l"(b), "l"(c));
    return r;
}

// distance pair for packed pixel pair vs packed negated pooled
#define DIST2(pa, pe, pf, n0, n1, n2, dout) do {                 \
    unsigned long long _dx = add2((pa), (n0));                   \
    unsigned long long _dy = add2((pe), (n1));                   \
    unsigned long long _dz = add2((pf), (n2));                   \
    (dout) = fma2(_dz, _dz, fma2(_dy, _dy, mul2(_dx, _dx)));     \
} while (0)

// ---------------------------------------------------------------------------
// Single fused kernel. CTA = (chunk, group, b): 4 pairs of image b over an
// 8192-pixel chunk.
//   Pass 1 (branchless, subsampled 1/4): per-thread min over first quarter ->
//     T = BLOCK-wide 5th-smallest thread-min (via per-warp 5-smallest, then a
//     40-value warp select). Guarantee: >=5 distinct threads have min <= T,
//     each contributing >=1 subset pixel <= T, subset is inside the chunk ->
//     pass 2 finds >=5 candidates. E[count]~20; P(count>CAP=192)~1e-15.
//     (R13 bug: min-of-warp-5ths gave E[count]~65 with ~10% overflow of
//      CAP=96 -> dropped candidates -> rel_err 3e-2.)
//   Pass 2 (full chunk): recompute d bit-identically, collect d <= T, exact
//     warp top-5 select with (d_bits<<32)|idx lexicographic keys.
//   Last CTA (fence + counter): merge chunks + roll/argmin/loss -> out.
// ---------------------------------------------------------------------------
__global__ void __launch_bounds__(THREADS, 4) cc_kernel(const float* __restrict__ preds,
                                                        const float* __restrict__ ref,
                                                        float* __restrict__ out) {
    const int chunk = blockIdx.x;
    const int group = blockIdx.y;
    const int b     = blockIdx.z;
    const int t = threadIdx.x, lane = t & 31, warp = t >> 5;

    // --- pooled colors for this CTA's 4 pairs (negated for add2-as-sub) ---
    __shared__ float s_p[GP][3];
    if (t < GP) {
        int l = group * GP + t;          // pair = b*64 + l
        int r = l * BS + b;              // flat row in pos_flat
        int sb = r >> 6, sl = r & 63;
        float x = preds[(sb * LEN + sl) * 8 + 0];
        float y = preds[(sb * LEN + sl) * 8 + 1];
        float cx = x * 256.0f - 0.5f;
        float cy = y * 256.0f - 0.5f;
        int ix = (int)rintf(cx);         // round-half-even == jnp.rint
        int iy = (int)rintf(cy);
        float v0 = 0.0f, v1 = 0.0f, v2 = 0.0f;
        if (ix >= 0 && ix < IMG && iy >= 0 && iy < IMG) {
            int off = iy * IMG + ix;
            v0 = ref[(b * 3 + 0) * NPIX + off];
            v1 = ref[(b * 3 + 1) * NPIX + off];
            v2 = ref[(b * 3 + 2) * NPIX + off];
        }
        s_p[t][0] = -v0; s_p[t][1] = -v1; s_p[t][2] = -v2;
    }
    __syncthreads();

    unsigned long long np[GP][3];        // packed (-p, -p)
#pragma unroll
    for (int j = 0; j < GP; j++)
#pragma unroll
        for (int c = 0; c < 3; c++) { float v = s_p[j][c]; np[j][c] = pk2(v, v); }

    // 128-bit loads land as two packed f32x2 (x,y) (z,w) — no pack movs
    const ulonglong2* __restrict__ r0 = (const ulonglong2*)(ref + (size_t)(b * 3 + 0) * NPIX);
    const ulonglong2* __restrict__ r1 = (const ulonglong2*)(ref + (size_t)(b * 3 + 1) * NPIX);
    const ulonglong2* __restrict__ r2 = (const ulonglong2*)(ref + (size_t)(b * 3 + 2) * NPIX);

    // ========== PASS 1 (subsampled): per-thread min per pair ==========
    float mn[GP];
#pragma unroll
    for (int j = 0; j < GP; j++) mn[j] = 3e38f;

#pragma unroll
    for (int i = 0; i < P1_ITERS; i++) {
        int gi = chunk * F4_PER_CHUNK + i * THREADS + t;   // coalesced 16B
        ulonglong2 a = r0[gi];
        ulonglong2 e = r1[gi];
        ulonglong2 f = r2[gi];
#pragma unroll
        for (int j = 0; j < GP; j++) {
            unsigned long long d01, d23;
            DIST2(a.x, e.x, f.x, np[j][0], np[j][1], np[j][2], d01);
            DIST2(a.y, e.y, f.y, np[j][0], np[j][1], np[j][2], d23);
            float d0, d1, d2, d3;
            upk2(d01, d0, d1);
            upk2(d23, d2, d3);
            mn[j] = fminf(mn[j], fminf(fminf(d0, d1), fminf(d2, d3)));
        }
    }

    // Per pair: each warp emits its 5 smallest thread-mins (with removal).
    __shared__ float sW[GP][8][KSEL];
#pragma unroll
    for (int j = 0; j < GP; j++) {
        float m = mn[j];
#pragma unroll
        for (int k = 0; k < KSEL; k++) {
            float w = m;
#pragma unroll
            for (int off = 16; off; off >>= 1) w = fminf(w, __shfl_xor_sync(0xffffffffu, w, off));
            if (m == w) m = 3e38f;       // remove all ties -> later rounds only grow: safe
            if (lane == 0) sW[j][warp][k] = w;
        }
    }
    __syncthreads();

    // Warps 0..3: pair j's block 5th-smallest thread-min from the 40 values.
    __shared__ float sTj[GP];
    if (warp < GP) {
        const float* w40 = &sW[warp][0][0];            // 40 floats
        float v0 = (lane      < 40) ? w40[lane]      : 3e38f;
        float v1 = (lane + 32 < 40) ? w40[lane + 32] : 3e38f;
        float T = 3e38f;
#pragma unroll
        for (int k = 0; k < KSEL; k++) {
            float m = fminf(v0, v1);
#pragma unroll
            for (int off = 16; off; off >>= 1) m = fminf(m, __shfl_xor_sync(0xffffffffu, m, off));
            T = m;
            if (v0 == m) v0 = 3e38f;     // remove ties: T only grows, still >=5 below
            if (v1 == m) v1 = 3e38f;
        }
        if (lane == 0) sTj[warp] = T;
    }
    __syncthreads();

    float Tj[GP];
#pragma unroll
    for (int j = 0; j < GP; j++) Tj[j] = sTj[j];       // >=5 chunk pixels <= Tj

    // ========== PASS 2 (full chunk): collect candidates d <= T ==========
    __shared__ unsigned long long cand[GP][CAP];
    __shared__ int cnt[GP];
    if (t < GP) cnt[t] = 0;
    __syncthreads();

#pragma unroll 2
    for (int i = 0; i < ITERS; i++) {
        int gi = chunk * F4_PER_CHUNK + i * THREADS + t;
        ulonglong2 a = r0[gi];
        ulonglong2 e = r1[gi];
        ulonglong2 f = r2[gi];
        int base = gi * 4;
#pragma unroll
        for (int j = 0; j < GP; j++) {
            unsigned long long d01, d23;
            DIST2(a.x, e.x, f.x, np[j][0], np[j][1], np[j][2], d01);
            DIST2(a.y, e.y, f.y, np[j][0], np[j][1], np[j][2], d23);
            float d0, d1, d2, d3;
            upk2(d01, d0, d1);
            upk2(d23, d2, d3);
            float m = fminf(fminf(d0, d1), fminf(d2, d3));
            float T = Tj[j];
            if (m <= T) {                 // rare path
                if (d0 <= T) { int s = atomicAdd(&cnt[j], 1);
                    if (s < CAP) cand[j][s] = ((unsigned long long)__float_as_uint(d0) << 32) | (unsigned int)(base + 0); }
                if (d1 <= T) { int s = atomicAdd(&cnt[j], 1);
                    if (s < CAP) cand[j][s] = ((unsigned long long)__float_as_uint(d1) << 32) | (unsigned int)(base + 1); }
                if (d2 <= T) { int s = atomicAdd(&cnt[j], 1);
                    if (s < CAP) cand[j][s] = ((unsigned long long)__float_as_uint(d2) << 32) | (unsigned int)(base + 2); }
                if (d3 <= T) { int s = atomicAdd(&cnt[j], 1);
                    if (s < CAP) cand[j][s] = ((unsigned long long)__float_as_uint(d3) << 32) | (unsigned int)(base + 3); }
            }
        }
    }
    __syncthreads();

    // Warps 0..3: warp j selects exact top-5 of pair j's candidates.
    if (warp < GP) {
        int j = warp;
        int n = cnt[j] < CAP ? cnt[j] : CAP;   // n >= 5 guaranteed by T
        unsigned long long v0 = ~0ull, v1 = ~0ull, v2 = ~0ull,
                           v3 = ~0ull, v4 = ~0ull, v5 = ~0ull;
        if (lane       < n) v0 = cand[j][lane];
        if (lane + 32  < n) v1 = cand[j][lane + 32];
        if (lane + 64  < n) v2 = cand[j][lane + 64];
        if (lane + 96  < n) v3 = cand[j][lane + 96];
        if (lane + 128 < n) v4 = cand[j][lane + 128];
        if (lane + 160 < n) v5 = cand[j][lane + 160];
        int pair = b * LEN + group * GP + j;
#pragma unroll
        for (int k = 0; k < KSEL; k++) {
            unsigned long long m = v0 < v1 ? v0 : v1;
            if (v2 < m) m = v2;
            if (v3 < m) m = v3;
            if (v4 < m) m = v4;
            if (v5 < m) m = v5;
#pragma unroll
            for (int off = 16; off; off >>= 1) {
                unsigned long long o = __shfl_xor_sync(0xffffffffu, m, off);
                if (o < m) m = o;
            }
            if (lane == 0) g_part[pair][chunk][k] = m;
            if (v0 == m) v0 = ~0ull;
            if (v1 == m) v1 = ~0ull;
            if (v2 == m) v2 = ~0ull;
            if (v3 == m) v3 = ~0ull;
            if (v4 == m) v4 = ~0ull;
            if (v5 == m) v5 = ~0ull;
        }
    }
    __threadfence();                      // release g_part before counter
    __syncthreads();

    // ================= last CTA: merge + loss ==============================
    __shared__ int isLast;
    if (t == 0) {
        int prev = atomicAdd(&g_done, 1);
        isLast = (prev == NCTAS - 1);
    }
    __syncthreads();
    if (!isLast) return;
    if (t == 0) g_done = 0;               // reset for next graph replay
    __threadfence();

    __shared__ unsigned int s_idx[NPAIR][KSEL];
#pragma unroll
    for (int rep = 0; rep < 2; rep++) {
        int p = t + rep * 256;
        unsigned long long b0 = ~0ull, b1 = ~0ull, b2 = ~0ull, b3 = ~0ull, b4 = ~0ull;
#pragma unroll
        for (int c = 0; c < CHUNKS; c++) {
#pragma unroll
            for (int k = 0; k < KSEL; k++) {
                unsigned long long v = g_part[p][c][k];
                if (v < b4) {
                    if (v < b3) { b4 = b3;
                        if (v < b2) { b3 = b2;
                            if (v < b1) { b2 = b1;
                                if (v < b0) { b1 = b0; b0 = v; } else b1 = v;
                            } else b2 = v;
                        } else b3 = v;
                    } else b4 = v;
                }
            }
        }
        s_idx[p][0] = (unsigned int)b0;
        s_idx[p][1] = (unsigned int)b1;
        s_idx[p][2] = (unsigned int)b2;
        s_idx[p][3] = (unsigned int)b3;
        s_idx[p][4] = (unsigned int)b4;
    }
    __syncthreads();

    float acc = 0.0f;
#pragma unroll
    for (int rep = 0; rep < 2; rep++) {
        int p = t + rep * 256;
        int pb = p >> 6, pl = p & 63;
        if (pl >= 1) {
            float px = preds[(pb * LEN + pl) * 8 + 0];
            float py = preds[(pb * LEN + pl) * 8 + 1];
            int src = pb * LEN + (pl - 1);        // tgt_down[b,l] = tgt[b,l-1]
            float bestD = 3e38f, bx = 0.0f, by = 0.0f;
#pragma unroll
            for (int k = 0; k < KSEL; k++) {
                unsigned int idx = s_idx[src][k];
                float tx = (float)(idx & 255u) * (1.0f / 256.0f);
                float ty = (float)(idx >> 8)   * (1.0f / 256.0f);
                float ddx = px - tx, ddy = py - ty;
                float dd = ddx * ddx + ddy * ddy;
                if (dd < bestD) { bestD = dd; bx = tx; by = ty; }  // first min wins
            }
            float ex = px - bx, ey = py - by;
            acc += ex * ex + ey * ey;
        }
    }

    __shared__ float s[256];
    s[t] = acc;
    __syncthreads();
    for (int st = 128; st; st >>= 1) {
        if (t < st) s[t] += s[t + st];
        __syncthreads();
    }
    if (t == 0) out[0] = s[0] / (float)(BS * (LEN - 1));
}

// ---------------------------------------------------------------------------
extern "C" void kernel_launch(void* const* d_in, const int* in_sizes, int n_in,
                              void* d_out, int out_size) {
    const float* preds = (const float*)d_in[0];   // (8, 64, 8) float32
    const float* ref   = (const float*)d_in[1];   // (8, 3, 256, 256) float32
    float* out = (float*)d_out;

    dim3 grid(CHUNKS, GROUPS, BS);
    cc_kernel<<<grid, THREADS>>>(preds, ref, out);
}

// round 17
// speedup vs baseline: 1.3438x; 1.3438x over previous
#include <cuda_runtime.h>
#include <cstdint>

#define IMG    256
#define NPIX   (IMG*IMG)
#define BS     8
#define LEN    64
#define KSEL   5
#define NPAIR  (BS*LEN)
#define CHUNKS 8
#define GP     4                      // pairs per CTA
#define GROUPS (LEN/GP)               // 16
#define THREADS 256
#define F4_PER_CHUNK (NPIX/4/CHUNKS)  // 2048 float4 per chunk
#define ITERS (F4_PER_CHUNK/THREADS)  // 8
#define P1_ITERS 2                    // pass-1 subsample: first 1/4 of chunk
#define CAP    192                    // candidate buffer per pair per CTA
#define NCTAS  (CHUNKS*GROUPS*BS)     // 1024

// partial top-5 per (pair, chunk), packed key = (float_bits(d)<<32)|idx
__device__ unsigned long long g_part[NPAIR][CHUNKS][KSEL];
__device__ int g_done;                // zero-init; reset by last CTA each launch

// ---------------- packed f32x2 helpers (bitwise identical to 2x scalar) ----
__device__ __forceinline__ unsigned long long pk2(float lo, float hi) {
    unsigned long long r;
    asm("mov.b64 %0,{%1,%2};" : "=l"(r) : "f"(lo), "f"(hi));
    return r;
}
__device__ __forceinline__ void upk2(unsigned long long v, float& lo, float& hi) {
    asm("mov.b64 {%0,%1},%2;" : "=f"(lo), "=f"(hi) : "l"(v));
}
__device__ __forceinline__ unsigned long long add2(unsigned long long a, unsigned long long b) {
    unsigned long long r;
    asm("add.rn.f32x2 %0,%1,%2;" : "=l"(r) : "l"(a), "l"(b));
    return r;
}
__device__ __forceinline__ unsigned long long mul2(unsigned long long a, unsigned long long b) {
    unsigned long long r;
    asm("mul.rn.f32x2 %0,%1,%2;" : "=l"(r) : "l"(a), "l"(b));
    return r;
}
__device__ __forceinline__ unsigned long long fma2(unsigned long long a, unsigned long long b,
                                                   unsigned long long c) {
    unsigned long long r;
    asm("fma.rn.f32x2 %0,%1,%2,%3;" : "=l"(r) : "l"(a), "l"(b), "l"(c));
    return r;
}

// distance pair for packed pixel pair vs packed negated pooled
#define DIST2(pa, pe, pf, n0, n1, n2, dout) do {                 \
    unsigned long long _dx = add2((pa), (n0));                   \
    unsigned long long _dy = add2((pe), (n1));                   \
    unsigned long long _dz = add2((pf), (n2));                   \
    (dout) = fma2(_dz, _dz, fma2(_dy, _dy, mul2(_dx, _dx)));     \
} while (0)

// ---------------------------------------------------------------------------
// Single fused kernel. CTA = (chunk, group, b): 4 pairs of image b over an
// 8192-pixel chunk.
//   Pass 1 (branchless, subsampled 1/4): per-thread min over first quarter ->
//     T = block-wide 5th-smallest thread-min. >=5 distinct threads (thus >=5
//     distinct chunk pixels) have d <= T -> pass 2 always finds >=5.
//     E[count]~20; P(count>CAP=192) negligible.
//   Pass 2 (full chunk): recompute d bit-identically, collect d <= T, exact
//     warp top-5 select with (d_bits<<32)|idx lexicographic keys.
//   Last CTA (fence + counter): merge chunks + roll/argmin/loss -> out.
// NOTE: occupancy 3 (not 4): pass-2 live set needs ~72 regs; forcing 62
// (R16) spilled to local and cost +40% issue count.
// ---------------------------------------------------------------------------
__global__ void __launch_bounds__(THREADS, 3) cc_kernel(const float* __restrict__ preds,
                                                        const float* __restrict__ ref,
                                                        float* __restrict__ out) {
    const int chunk = blockIdx.x;
    const int group = blockIdx.y;
    const int b     = blockIdx.z;
    const int t = threadIdx.x, lane = t & 31, warp = t >> 5;

    // --- pooled colors for this CTA's 4 pairs (negated for add2-as-sub) ---
    __shared__ float s_p[GP][3];
    if (t < GP) {
        int l = group * GP + t;          // pair = b*64 + l
        int r = l * BS + b;              // flat row in pos_flat
        int sb = r >> 6, sl = r & 63;
        float x = preds[(sb * LEN + sl) * 8 + 0];
        float y = preds[(sb * LEN + sl) * 8 + 1];
        float cx = x * 256.0f - 0.5f;
        float cy = y * 256.0f - 0.5f;
        int ix = (int)rintf(cx);         // round-half-even == jnp.rint
        int iy = (int)rintf(cy);
        float v0 = 0.0f, v1 = 0.0f, v2 = 0.0f;
        if (ix >= 0 && ix < IMG && iy >= 0 && iy < IMG) {
            int off = iy * IMG + ix;
            v0 = ref[(b * 3 + 0) * NPIX + off];
            v1 = ref[(b * 3 + 1) * NPIX + off];
            v2 = ref[(b * 3 + 2) * NPIX + off];
        }
        s_p[t][0] = -v0; s_p[t][1] = -v1; s_p[t][2] = -v2;
    }
    __syncthreads();

    unsigned long long np[GP][3];        // packed (-p, -p)
#pragma unroll
    for (int j = 0; j < GP; j++)
#pragma unroll
        for (int c = 0; c < 3; c++) { float v = s_p[j][c]; np[j][c] = pk2(v, v); }

    // 128-bit loads land as two packed f32x2 (x,y) (z,w) — no pack movs
    const ulonglong2* __restrict__ r0 = (const ulonglong2*)(ref + (size_t)(b * 3 + 0) * NPIX);
    const ulonglong2* __restrict__ r1 = (const ulonglong2*)(ref + (size_t)(b * 3 + 1) * NPIX);
    const ulonglong2* __restrict__ r2 = (const ulonglong2*)(ref + (size_t)(b * 3 + 2) * NPIX);

    // ========== PASS 1 (subsampled): per-thread min per pair ==========
    float mn[GP];
#pragma unroll
    for (int j = 0; j < GP; j++) mn[j] = 3e38f;

#pragma unroll
    for (int i = 0; i < P1_ITERS; i++) {
        int gi = chunk * F4_PER_CHUNK + i * THREADS + t;   // coalesced 16B
        ulonglong2 a = r0[gi];
        ulonglong2 e = r1[gi];
        ulonglong2 f = r2[gi];
#pragma unroll
        for (int j = 0; j < GP; j++) {
            unsigned long long d01, d23;
            DIST2(a.x, e.x, f.x, np[j][0], np[j][1], np[j][2], d01);
            DIST2(a.y, e.y, f.y, np[j][0], np[j][1], np[j][2], d23);
            float d0, d1, d2, d3;
            upk2(d01, d0, d1);
            upk2(d23, d2, d3);
            mn[j] = fminf(mn[j], fminf(fminf(d0, d1), fminf(d2, d3)));
        }
    }

    // Per pair: each warp emits its 5 smallest thread-mins (with removal).
    __shared__ float sW[GP][8][KSEL];
#pragma unroll
    for (int j = 0; j < GP; j++) {
        float m = mn[j];
#pragma unroll
        for (int k = 0; k < KSEL; k++) {
            float w = m;
#pragma unroll
            for (int off = 16; off; off >>= 1) w = fminf(w, __shfl_xor_sync(0xffffffffu, w, off));
            if (m == w) m = 3e38f;       // remove all ties -> later rounds only grow: safe
            if (lane == 0) sW[j][warp][k] = w;
        }
    }
    __syncthreads();

    // Warps 0..3: pair j's block 5th-smallest thread-min from the 40 values.
    __shared__ float sTj[GP];
    if (warp < GP) {
        const float* w40 = &sW[warp][0][0];            // 40 floats
        float v0 = (lane      < 40) ? w40[lane]      : 3e38f;
        float v1 = (lane + 32 < 40) ? w40[lane + 32] : 3e38f;
        float T = 3e38f;
#pragma unroll
        for (int k = 0; k < KSEL; k++) {
            float m = fminf(v0, v1);
#pragma unroll
            for (int off = 16; off; off >>= 1) m = fminf(m, __shfl_xor_sync(0xffffffffu, m, off));
            T = m;
            if (v0 == m) v0 = 3e38f;     // remove ties: T only grows, still >=5 below
            if (v1 == m) v1 = 3e38f;
        }
        if (lane == 0) sTj[warp] = T;
    }
    __syncthreads();

    float Tj[GP];
#pragma unroll
    for (int j = 0; j < GP; j++) Tj[j] = sTj[j];       // >=5 chunk pixels <= Tj

    // ========== PASS 2 (full chunk): collect candidates d <= T ==========
    __shared__ unsigned long long cand[GP][CAP];
    __shared__ int cnt[GP];
    if (t < GP) cnt[t] = 0;
    __syncthreads();

#pragma unroll 2
    for (int i = 0; i < ITERS; i++) {
        int gi = chunk * F4_PER_CHUNK + i * THREADS + t;
        ulonglong2 a = r0[gi];
        ulonglong2 e = r1[gi];
        ulonglong2 f = r2[gi];
        int base = gi * 4;
#pragma unroll
        for (int j = 0; j < GP; j++) {
            unsigned long long d01, d23;
            DIST2(a.x, e.x, f.x, np[j][0], np[j][1], np[j][2], d01);
            DIST2(a.y, e.y, f.y, np[j][0], np[j][1], np[j][2], d23);
            float d0, d1, d2, d3;
            upk2(d01, d0, d1);
            upk2(d23, d2, d3);
            float m = fminf(fminf(d0, d1), fminf(d2, d3));
            float T = Tj[j];
            if (m <= T) {                 // rare path
                if (d0 <= T) { int s = atomicAdd(&cnt[j], 1);
                    if (s < CAP) cand[j][s] = ((unsigned long long)__float_as_uint(d0) << 32) | (unsigned int)(base + 0); }
                if (d1 <= T) { int s = atomicAdd(&cnt[j], 1);
                    if (s < CAP) cand[j][s] = ((unsigned long long)__float_as_uint(d1) << 32) | (unsigned int)(base + 1); }
                if (d2 <= T) { int s = atomicAdd(&cnt[j], 1);
                    if (s < CAP) cand[j][s] = ((unsigned long long)__float_as_uint(d2) << 32) | (unsigned int)(base + 2); }
                if (d3 <= T) { int s = atomicAdd(&cnt[j], 1);
                    if (s < CAP) cand[j][s] = ((unsigned long long)__float_as_uint(d3) << 32) | (unsigned int)(base + 3); }
            }
        }
    }
    __syncthreads();

    // Warps 0..3: warp j selects exact top-5 of pair j's candidates.
    if (warp < GP) {
        int j = warp;
        int n = cnt[j] < CAP ? cnt[j] : CAP;   // n >= 5 guaranteed by T
        unsigned long long v0 = ~0ull, v1 = ~0ull, v2 = ~0ull,
                           v3 = ~0ull, v4 = ~0ull, v5 = ~0ull;
        if (lane       < n) v0 = cand[j][lane];
        if (lane + 32  < n) v1 = cand[j][lane + 32];
        if (lane + 64  < n) v2 = cand[j][lane + 64];
        if (lane + 96  < n) v3 = cand[j][lane + 96];
        if (lane + 128 < n) v4 = cand[j][lane + 128];
        if (lane + 160 < n) v5 = cand[j][lane + 160];
        int pair = b * LEN + group * GP + j;
#pragma unroll
        for (int k = 0; k < KSEL; k++) {
            unsigned long long m = v0 < v1 ? v0 : v1;
            if (v2 < m) m = v2;
            if (v3 < m) m = v3;
            if (v4 < m) m = v4;
            if (v5 < m) m = v5;
#pragma unroll
            for (int off = 16; off; off >>= 1) {
                unsigned long long o = __shfl_xor_sync(0xffffffffu, m, off);
                if (o < m) m = o;
            }
            if (lane == 0) g_part[pair][chunk][k] = m;
            if (v0 == m) v0 = ~0ull;
            if (v1 == m) v1 = ~0ull;
            if (v2 == m) v2 = ~0ull;
            if (v3 == m) v3 = ~0ull;
            if (v4 == m) v4 = ~0ull;
            if (v5 == m) v5 = ~0ull;
        }
    }
    __threadfence();                      // release g_part before counter
    __syncthreads();

    // ================= last CTA: merge + loss ==============================
    __shared__ int isLast;
    if (t == 0) {
        int prev = atomicAdd(&g_done, 1);
        isLast = (prev == NCTAS - 1);
    }
    __syncthreads();
    if (!isLast) return;
    if (t == 0) g_done = 0;               // reset for next graph replay
    __threadfence();

    __shared__ unsigned int s_idx[NPAIR][KSEL];
#pragma unroll
    for (int rep = 0; rep < 2; rep++) {
        int p = t + rep * 256;
        unsigned long long b0 = ~0ull, b1 = ~0ull, b2 = ~0ull, b3 = ~0ull, b4 = ~0ull;
#pragma unroll
        for (int c = 0; c < CHUNKS; c++) {
#pragma unroll
            for (int k = 0; k < KSEL; k++) {
                unsigned long long v = g_part[p][c][k];
                if (v < b4) {
                    if (v < b3) { b4 = b3;
                        if (v < b2) { b3 = b2;
                            if (v < b1) { b2 = b1;
                                if (v < b0) { b1 = b0; b0 = v; } else b1 = v;
                            } else b2 = v;
                        } else b3 = v;
                    } else b4 = v;
                }
            }
        }
        s_idx[p][0] = (unsigned int)b0;
        s_idx[p][1] = (unsigned int)b1;
        s_idx[p][2] = (unsigned int)b2;
        s_idx[p][3] = (unsigned int)b3;
        s_idx[p][4] = (unsigned int)b4;
    }
    __syncthreads();

    float acc = 0.0f;
#pragma unroll
    for (int rep = 0; rep < 2; rep++) {
        int p = t + rep * 256;
        int pb = p >> 6, pl = p & 63;
        if (pl >= 1) {
            float px = preds[(pb * LEN + pl) * 8 + 0];
            float py = preds[(pb * LEN + pl) * 8 + 1];
            int src = pb * LEN + (pl - 1);        // tgt_down[b,l] = tgt[b,l-1]
            float bestD = 3e38f, bx = 0.0f, by = 0.0f;
#pragma unroll
            for (int k = 0; k < KSEL; k++) {
                unsigned int idx = s_idx[src][k];
                float tx = (float)(idx & 255u) * (1.0f / 256.0f);
                float ty = (float)(idx >> 8)   * (1.0f / 256.0f);
                float ddx = px - tx, ddy = py - ty;
                float dd = ddx * ddx + ddy * ddy;
                if (dd < bestD) { bestD = dd; bx = tx; by = ty; }  // first min wins
            }
            float ex = px - bx, ey = py - by;
            acc += ex * ex + ey * ey;
        }
    }

    __shared__ float s[256];
    s[t] = acc;
    __syncthreads();
    for (int st = 128; st; st >>= 1) {
        if (t < st) s[t] += s[t + st];
        __syncthreads();
    }
    if (t == 0) out[0] = s[0] / (float)(BS * (LEN - 1));
}

// ---------------------------------------------------------------------------
extern "C" void kernel_launch(void* const* d_in, const int* in_sizes, int n_in,
                              void* d_out, int out_size) {
    const float* preds = (const float*)d_in[0];   // (8, 64, 8) float32
    const float* ref   = (const float*)d_in[1];   // (8, 3, 256, 256) float32
    float* out = (float*)d_out;

    dim3 grid(CHUNKS, GROUPS, BS);
    cc_kernel<<<grid, THREADS>>>(preds, ref, out);
}